// round 15
// baseline (speedup 1.0000x reference)
#include <cuda_runtime.h>
#include <math.h>

// Fixed shapes: x is (4,3,64,64) fp32
#define HW      4096
#define NCH     12
#define NOFF    16129        // 127*127 offsets
#define NBINS   7939
#define SOFF_N  1024         // unrolled hot-path offsets
#define CH      16           // chunk size
#define STRIDE  128          // window row stride
#define R_C     19           // window slot of block's first row
#define WIN     40           // window rows
#define PLANE_F (WIN * STRIDE)       // 5120 floats = 20KB

struct Tables {
    int   off[NOFF];   // dy*STRIDE + dx   (window delta; hot + replay)
    float d2[NOFF];
    int   pk[NOFF];    // dy*65536 | (dx & 0xFFFF)  (cold tail, exact decode)
};

constexpr Tables make_tables() {
    Tables t{};
    int hist[NBINS] = {};
    for (int dy = -63; dy <= 63; ++dy)
        for (int dx = -63; dx <= 63; ++dx)
            hist[dy * dy + dx * dx]++;
    int start[NBINS] = {};
    int acc = 0;
    for (int b = 0; b < NBINS; ++b) { start[b] = acc; acc += hist[b]; }
    for (int dy = -63; dy <= 63; ++dy)
        for (int dx = -63; dx <= 63; ++dx) {
            int d2  = dy * dy + dx * dx;
            int pos = start[d2]++;
            t.off[pos] = dy * STRIDE + dx;
            t.d2[pos]  = (float)d2;
            t.pk[pos]  = dy * 65536 | (dx & 0xFFFF);
        }
    return t;
}

// Constant-indexed accesses (fully unrolled hot loop) fold to literals;
// runtime-indexed accesses read the constant global.
__device__ constexpr Tables g_tab = make_tables();

constexpr int d2_last_staged() {
    int hist[NBINS] = {};
    for (int dy = -63; dy <= 63; ++dy)
        for (int dx = -63; dx <= 63; ++dx)
            hist[dy * dy + dx * dx]++;
    int acc = 0;
    for (int b = 0; b < NBINS; ++b) { acc += hist[b]; if (acc >= SOFF_N) return b; }
    return NBINS - 1;
}
constexpr int isqrt_c(int v) { int s = 0; while ((s + 1) * (s + 1) <= v) ++s; return s; }
static_assert(isqrt_c(d2_last_staged()) <= R_C - 1,            "top margin");
static_assert(isqrt_c(d2_last_staged()) <= WIN - 2 - (R_C + 1),"bottom margin");
static_assert(isqrt_c(d2_last_staged()) <= 32,                 "side margin");

// smem: window 20KB + replay table 8KB + 4 reduction words
#define SMEM_BYTES ((PLANE_F + SOFF_N * 2 + 8) * 4)

// 128 threads = 1 thread per pixel, 2 adjacent rows per block.
// 32 row-pairs per channel, 384 blocks; deepest pairs launch first.
__global__ __launch_bounds__(128) void k_main(const float* __restrict__ x,
                                              float* __restrict__ out) {
    extern __shared__ float smem[];
    float*  swp   = smem;                    // [40][128] window, zero margins
    float2* stab  = (float2*)(smem + PLANE_F);   // replay table (off bits, d2)
    float*  red   = smem + PLANE_F + SOFF_N * 2; // 4 warp partials

    const int tid = threadIdx.x;
    const int bc  = blockIdx.x % NCH;        // channel varies fastest
    const int rp  = blockIdx.x / NCH;        // depth rank of row-pair (0..31)
    const int pr  = (rp & 1) ? 31 - (rp >> 1) : (rp >> 1);  // deep-first pair
    const int pi0 = pr * 2;                  // first row of the pair
    const float* __restrict__ plane = x + bc * HW;

    // --- Prologue 1: zero window + stage replay table (disjoint regions) ---
    #pragma unroll
    for (int m = tid; m < WIN * 32; m += 128)
        ((float4*)swp)[m] = make_float4(0.f, 0.f, 0.f, 0.f);
    #pragma unroll
    for (int i = tid; i < SOFF_N; i += 128)  // 8 coalesced float2 per thread
        stab[i] = make_float2(__int_as_float(g_tab.off[i]), g_tab.d2[i]);
    __syncthreads();

    // --- Prologue 2: full-plane sum (for bound) + windowed fill ---
    float acc = 0.f;
    #pragma unroll
    for (int i = tid; i < 1024; i += 128) {
        float4 v = ((const float4*)plane)[i];
        acc += v.x + v.y + v.z + v.w;
        int slot = (i >> 4) - pi0 + R_C;
        if ((unsigned)slot < (unsigned)WIN)
            ((float4*)swp)[slot * 32 + 8 + (i & 15)] = v;
    }
    #pragma unroll
    for (int d = 16; d > 0; d >>= 1)
        acc += __shfl_xor_sync(0xFFFFFFFFu, acc, d);
    if ((tid & 31) == 0) red[tid >> 5] = acc;
    __syncthreads();
    const float bound = 0.05f * ((red[0] + red[1]) + (red[2] + red[3]));

    const int rl = tid >> 6;                 // row within pair (0/1)
    const int pj = tid & 63;                 // column
    const int pi = pi0 + rl;
    const int pc = (R_C + rl) * STRIDE + 32 + pj;

    float cw   = 0.f, qacc = 0.f;
    float cw0  = 0.f, q0 = 0.f;
    int   t_cr = -1;
    bool  done = false;
    bool  alive = true;

    // --- Hot loop: fully unrolled; offsets/d2 folded to immediates ---
    #pragma unroll
    for (int t0 = 0; t0 < SOFF_N; t0 += 2 * CH) {
        if (alive) {
            #pragma unroll
            for (int c = 0; c < 2; ++c) {
                const int tb = t0 + c * CH;
                float w[CH];
                #pragma unroll
                for (int k = 0; k < CH; ++k)
                    w[k] = swp[pc + g_tab.off[tb + k]];   // LDS [pc + imm]
                float sa = ((w[0] + w[1]) + (w[2] + w[3]))
                         + ((w[4] + w[5]) + (w[6] + w[7]));
                float sb = ((w[8] + w[9]) + (w[10] + w[11]))
                         + ((w[12] + w[13]) + (w[14] + w[15]));
                float s16 = sa + sb;
                float qa = w[0] * g_tab.d2[tb];
                float qb = w[8] * g_tab.d2[tb + 8];
                #pragma unroll
                for (int k = 1; k < 8; ++k) {
                    qa = fmaf(w[k],     g_tab.d2[tb + k],     qa);
                    qb = fmaf(w[k + 8], g_tab.d2[tb + k + 8], qb);
                }
                bool cross = (!done) & (cw + s16 >= bound);
                if (cross) { t_cr = tb; cw0 = cw; q0 = qacc; done = true; }
                cw   += s16;
                qacc += qa + qb;
            }
            alive = (__ballot_sync(0xFFFFFFFFu, !done) != 0u);
        }
    }

    // --- Epilogue: one uniform replay per thread (smem table reads) ---
    float cs0 = done ? q0 : qacc;
    float cwX = done ? cw0 : cw;

    float val = 0.f;
    bool  found = false;
    int   t_tail = NOFF;
    if (done) {
        float cwl = cwX, csl = cs0;
        float wv[CH], dv[CH];
        #pragma unroll
        for (int k = 0; k < CH; ++k) {
            float2 e = stab[t_cr + k];
            wv[k] = swp[pc + __float_as_int(e.x)];
            dv[k] = e.y;
        }
        #pragma unroll
        for (int k = 0; k < CH; ++k) {
            cwl += wv[k];
            csl += dv[k] * wv[k];
            if (!found && cwl >= bound) {
                val = csl + dv[k] * (bound - cwl);
                found = true;
            }
        }
        if (!found) { t_tail = t_cr + CH; cwX = cwl; cs0 = csl; } // ulp slip
    } else {
        t_tail = SOFF_N;
    }

    // --- Cold exact tail (essentially never taken): global gathers ---
    if (t_tail < NOFF) {
        float cwl = cwX, csl = cs0;
        #pragma unroll 1
        for (int t = t_tail; t < NOFF && !found; ++t) {
            int pk   = g_tab.pk[t];
            float d2 = g_tab.d2[t];
            int dy   = pk >> 16;
            int dx   = (int)(short)(pk & 0xFFFF);
            int ni   = pi + dy, nj = pj + dx;
            float w  = 0.f;
            if (((unsigned)ni < 64u) & ((unsigned)nj < 64u))
                w = plane[ni * 64 + nj];
            cwl += w;
            csl += d2 * w;
            if (cwl >= bound) { val = csl + d2 * (bound - cwl); found = true; }
        }
        if (!found) val = csl;
    }

    out[bc * HW + pi * 64 + pj] = sqrtf(val / bound);
}

// ---------------------------------------------------------------------------
extern "C" void kernel_launch(void* const* d_in, const int* in_sizes, int n_in,
                              void* d_out, int out_size) {
    const float* x = (const float*)d_in[0];
    float* out = (float*)d_out;
    cudaFuncSetAttribute(k_main, cudaFuncAttributeMaxDynamicSharedMemorySize,
                         SMEM_BYTES);
    k_main<<<NCH * 32, 128, SMEM_BYTES>>>(x, out);
}

// round 16
// speedup vs baseline: 1.1940x; 1.1940x over previous
#include <cuda_runtime.h>
#include <math.h>

// Fixed shapes: x is (4,3,64,64) fp32
#define HW      4096
#define NCH     12
#define NOFF    16129        // 127*127 offsets
#define NBINS   7939
#define SOFF_N  1024         // unrolled hot-path offsets
#define CH      16           // chunk size
#define STRIDE  128          // window row stride
#define R_C     19           // window slot of block's first row
#define WIN     40           // window rows
#define PLANE_F (WIN * STRIDE)       // 5120 floats = 20KB
#define OBIAS   2464         // = min pc = R_C*STRIDE+32; makes LDS imms >= 0

struct Tables {
    int   off[NOFF];   // dy*STRIDE + dx + OBIAS  (window delta, biased)
    float d2[NOFF];
    int   pk[NOFF];    // dy*65536 | (dx & 0xFFFF)  (cold tail, exact decode)
};

constexpr Tables make_tables() {
    Tables t{};
    int hist[NBINS] = {};
    for (int dy = -63; dy <= 63; ++dy)
        for (int dx = -63; dx <= 63; ++dx)
            hist[dy * dy + dx * dx]++;
    int start[NBINS] = {};
    int acc = 0;
    for (int b = 0; b < NBINS; ++b) { start[b] = acc; acc += hist[b]; }
    for (int dy = -63; dy <= 63; ++dy)
        for (int dx = -63; dx <= 63; ++dx) {
            int d2  = dy * dy + dx * dx;
            int pos = start[d2]++;
            t.off[pos] = dy * STRIDE + dx + OBIAS;
            t.d2[pos]  = (float)d2;
            t.pk[pos]  = dy * 65536 | (dx & 0xFFFF);
        }
    return t;
}

// Constant-indexed accesses (fully unrolled hot loop) fold to literals;
// runtime-indexed accesses read the constant global.
__device__ constexpr Tables g_tab = make_tables();

constexpr int d2_last_staged() {
    int hist[NBINS] = {};
    for (int dy = -63; dy <= 63; ++dy)
        for (int dx = -63; dx <= 63; ++dx)
            hist[dy * dy + dx * dx]++;
    int acc = 0;
    for (int b = 0; b < NBINS; ++b) { acc += hist[b]; if (acc >= SOFF_N) return b; }
    return NBINS - 1;
}
constexpr int isqrt_c(int v) { int s = 0; while ((s + 1) * (s + 1) <= v) ++s; return s; }
static_assert(isqrt_c(d2_last_staged()) <= R_C - 1,            "top margin");
static_assert(isqrt_c(d2_last_staged()) <= WIN - 2 - (R_C + 1),"bottom margin");
static_assert(isqrt_c(d2_last_staged()) <= 32,                 "side margin");

// smem: window 20KB + replay table 8KB + 4 reduction words
#define SMEM_BYTES ((PLANE_F + SOFF_N * 2 + 8) * 4)

// 128 threads = 1 thread per pixel, 2 adjacent rows per block.
// 32 row-pairs per channel, 384 blocks; deepest pairs launch first.
__global__ __launch_bounds__(128) void k_main(const float* __restrict__ x,
                                              float* __restrict__ out) {
    extern __shared__ float smem[];
    float*  swp  = smem;                     // [40][128] window, zero margins
    float2* stab = (float2*)(smem + PLANE_F);    // replay table (biased off, d2)
    float*  red  = smem + PLANE_F + SOFF_N * 2;  // 4 warp partials

    const int tid = threadIdx.x;
    const int bc  = blockIdx.x % NCH;        // channel varies fastest
    const int rp  = blockIdx.x / NCH;        // depth rank of row-pair (0..31)
    const int pr  = (rp & 1) ? 31 - (rp >> 1) : (rp >> 1);  // deep-first pair
    const int pi0 = pr * 2;                  // first row of the pair
    const float* __restrict__ plane = x + bc * HW;

    // --- Prologue 1: zero window + stage replay table (disjoint regions) ---
    #pragma unroll
    for (int m = tid; m < WIN * 32; m += 128)
        ((float4*)swp)[m] = make_float4(0.f, 0.f, 0.f, 0.f);
    #pragma unroll
    for (int i = tid; i < SOFF_N; i += 128)  // 8 coalesced float2 per thread
        stab[i] = make_float2(__int_as_float(g_tab.off[i]), g_tab.d2[i]);
    __syncthreads();

    // --- Prologue 2: full-plane sum (for bound) + windowed fill ---
    float acc = 0.f;
    #pragma unroll
    for (int i = tid; i < 1024; i += 128) {
        float4 v = ((const float4*)plane)[i];
        acc += v.x + v.y + v.z + v.w;
        int slot = (i >> 4) - pi0 + R_C;
        if ((unsigned)slot < (unsigned)WIN)
            ((float4*)swp)[slot * 32 + 8 + (i & 15)] = v;
    }
    #pragma unroll
    for (int d = 16; d > 0; d >>= 1)
        acc += __shfl_xor_sync(0xFFFFFFFFu, acc, d);
    if ((tid & 31) == 0) red[tid >> 5] = acc;
    __syncthreads();
    const float bound = 0.05f * ((red[0] + red[1]) + (red[2] + red[3]));

    const int rl = tid >> 6;                 // row within pair (0/1)
    const int pj = tid & 63;                 // column
    const int pi = pi0 + rl;
    const int pcb = (R_C + rl) * STRIDE + 32 + pj - OBIAS;  // biased base

    float cw   = 0.f, qacc = 0.f;
    float cw0  = 0.f, q0 = 0.f;
    int   t_cr = -1;
    bool  done = false;

    // --- Hot loop: fully unrolled, folded immediates, HARD break on ballot ---
    #pragma unroll
    for (int t0 = 0; t0 < SOFF_N; t0 += 2 * CH) {
        #pragma unroll
        for (int c = 0; c < 2; ++c) {
            const int tb = t0 + c * CH;
            float w[CH];
            #pragma unroll
            for (int k = 0; k < CH; ++k)
                w[k] = swp[pcb + g_tab.off[tb + k]];   // LDS [R + imm>=0]
            float sa = ((w[0] + w[1]) + (w[2] + w[3]))
                     + ((w[4] + w[5]) + (w[6] + w[7]));
            float sb = ((w[8] + w[9]) + (w[10] + w[11]))
                     + ((w[12] + w[13]) + (w[14] + w[15]));
            float s16 = sa + sb;
            float qa = w[0] * g_tab.d2[tb];
            float qb = w[8] * g_tab.d2[tb + 8];
            #pragma unroll
            for (int k = 1; k < 8; ++k) {
                qa = fmaf(w[k],     g_tab.d2[tb + k],     qa);
                qb = fmaf(w[k + 8], g_tab.d2[tb + k + 8], qb);
            }
            bool cross = (!done) & (cw + s16 >= bound);
            if (cross) { t_cr = tb; cw0 = cw; q0 = qacc; done = true; }
            cw   += s16;
            qacc += qa + qb;
        }
        if (__ballot_sync(0xFFFFFFFFu, !done) == 0u) break;  // jump out
    }

    // --- Epilogue: one uniform replay per thread (smem table reads) ---
    float cs0 = done ? q0 : qacc;
    float cwX = done ? cw0 : cw;

    float val = 0.f;
    bool  found = false;
    int   t_tail = NOFF;
    if (done) {
        float cwl = cwX, csl = cs0;
        float wv[CH], dv[CH];
        #pragma unroll
        for (int k = 0; k < CH; ++k) {
            float2 e = stab[t_cr + k];
            wv[k] = swp[pcb + __float_as_int(e.x)];
            dv[k] = e.y;
        }
        #pragma unroll
        for (int k = 0; k < CH; ++k) {
            cwl += wv[k];
            csl += dv[k] * wv[k];
            if (!found && cwl >= bound) {
                val = csl + dv[k] * (bound - cwl);
                found = true;
            }
        }
        if (!found) { t_tail = t_cr + CH; cwX = cwl; cs0 = csl; } // ulp slip
    } else {
        t_tail = SOFF_N;
    }

    // --- Cold exact tail (essentially never taken): global gathers ---
    if (t_tail < NOFF) {
        float cwl = cwX, csl = cs0;
        #pragma unroll 1
        for (int t = t_tail; t < NOFF && !found; ++t) {
            int pk   = g_tab.pk[t];
            float d2 = g_tab.d2[t];
            int dy   = pk >> 16;
            int dx   = (int)(short)(pk & 0xFFFF);
            int ni   = pi + dy, nj = pj + dx;
            float w  = 0.f;
            if (((unsigned)ni < 64u) & ((unsigned)nj < 64u))
                w = plane[ni * 64 + nj];
            cwl += w;
            csl += d2 * w;
            if (cwl >= bound) { val = csl + d2 * (bound - cwl); found = true; }
        }
        if (!found) val = csl;
    }

    out[bc * HW + pi * 64 + pj] = sqrtf(val / bound);
}

// ---------------------------------------------------------------------------
extern "C" void kernel_launch(void* const* d_in, const int* in_sizes, int n_in,
                              void* d_out, int out_size) {
    const float* x = (const float*)d_in[0];
    float* out = (float*)d_out;
    cudaFuncSetAttribute(k_main, cudaFuncAttributeMaxDynamicSharedMemorySize,
                         SMEM_BYTES);
    k_main<<<NCH * 32, 128, SMEM_BYTES>>>(x, out);
}